// round 3
// baseline (speedup 1.0000x reference)
#include <cuda_runtime.h>
#include <cuda_bf16.h>
#include <math.h>

// StyleLoss: x, target [B=8, C=256, H=128, W=128] fp32.
// loss = sum_{k=1..5} sqrt( sum_c (mu_k_x[c] - mu_k_t[c])^2 )
// Single pass: raw power sums S1..S5 per channel with packed f32x2 (FFMA2)
// math; binomial conversion to central moments in a fused last-block finalize.
// R3: __launch_bounds__(256,6) to recover 6 CTAs/SM occupancy lost to FFMA2
// register pairing; unroll 2 to cap hoisted-load register footprint.

#define B_DIM 8
#define C_DIM 256
#define HW_DIM (128 * 128)          // 16384 contiguous floats per (b,c) slice
#define N_PER_CH (B_DIM * HW_DIM)   // 131072 elements reduced per channel
#define N_CTA (B_DIM * C_DIM)       // 2048 blocks, one per (b,c) slice

// Per-CTA partial sums: [cta][10] = {S1..S5 of x, S1..S5 of target}.
__device__ float g_part[N_CTA * 10];
__device__ unsigned int g_count;    // zero-init at load; last block resets to 0

typedef unsigned long long u64;

#define MUL2(d, a, b) \
    asm("mul.rn.f32x2 %0, %1, %2;" : "=l"(d) : "l"(a), "l"(b))
#define ADD2(d, a, b) \
    asm("add.rn.f32x2 %0, %1, %2;" : "=l"(d) : "l"(a), "l"(b))
#define FMA2(d, a, b, c) \
    asm("fma.rn.f32x2 %0, %1, %2, %3;" : "=l"(d) : "l"(a), "l"(b), "l"(c))
#define UNPACK2(lo, hi, p) \
    asm("mov.b64 {%0, %1}, %2;" : "=f"(lo), "=f"(hi) : "l"(p))

// 5 power sums of a packed pair: 7 f32x2 ops for 2 elements.
__device__ __forceinline__ void acc5p(u64 v, u64* s) {
    u64 v2, v3;
    MUL2(v2, v, v);
    ADD2(s[0], s[0], v);
    FMA2(s[1], v, v, s[1]);
    FMA2(s[2], v2, v, s[2]);
    FMA2(s[3], v2, v2, s[3]);
    MUL2(v3, v2, v);
    FMA2(s[4], v3, v2, s[4]);
}

__global__ __launch_bounds__(256, 6) void style_fused(
        const float* __restrict__ x,
        const float* __restrict__ t,
        float* __restrict__ out) {
    const int cta = blockIdx.x;  // cta = b*C + c -> contiguous HW slice
    const ulonglong2* __restrict__ xp =
        reinterpret_cast<const ulonglong2*>(x) + (size_t)cta * (HW_DIM / 4);
    const ulonglong2* __restrict__ tp =
        reinterpret_cast<const ulonglong2*>(t) + (size_t)cta * (HW_DIM / 4);

    u64 sp[10];
#pragma unroll
    for (int j = 0; j < 10; j++) sp[j] = 0ull;

    // 16 x 16B iterations per thread per tensor; fully coalesced LDG.128.
    // unroll 2 -> 4 LDG.128 batched per body, 16 data regs live.
#pragma unroll 2
    for (int i = threadIdx.x; i < HW_DIM / 4; i += 256) {
        ulonglong2 v = xp[i];
        ulonglong2 w = tp[i];
        acc5p(v.x, sp); acc5p(v.y, sp);
        acc5p(w.x, sp + 5); acc5p(w.y, sp + 5);
    }

    // Unpack pairs, then warp tree-reduce the 10 scalar accumulators.
    float s[10];
#pragma unroll
    for (int j = 0; j < 10; j++) {
        float lo, hi;
        UNPACK2(lo, hi, sp[j]);
        s[j] = lo + hi;
    }
#pragma unroll
    for (int j = 0; j < 10; j++) {
#pragma unroll
        for (int o = 16; o > 0; o >>= 1)
            s[j] += __shfl_down_sync(0xffffffffu, s[j], o);
    }

    __shared__ float wred[8][10];
    const int lane = threadIdx.x & 31;
    const int wid  = threadIdx.x >> 5;
    if (lane == 0) {
#pragma unroll
        for (int j = 0; j < 10; j++) wred[wid][j] = s[j];
    }
    __syncthreads();

    if (threadIdx.x < 10) {
        float v = 0.0f;
#pragma unroll
        for (int w = 0; w < 8; w++) v += wred[w][threadIdx.x];
        g_part[cta * 10 + threadIdx.x] = v;
    }

    // ---- last-block fused finalize ----
    __shared__ int is_last;
    if (threadIdx.x == 0) {
        __threadfence();  // publish g_part before counting
        unsigned int prev = atomicAdd(&g_count, 1u);
        is_last = (prev == (unsigned int)(N_CTA - 1)) ? 1 : 0;
    }
    __syncthreads();
    if (!is_last) return;

    if (threadIdx.x == 0) g_count = 0;  // reset for next graph replay
    __threadfence();                     // acquire: see all g_part writes

    const int c = threadIdx.x;  // one thread per channel
    float f[10];
#pragma unroll
    for (int j = 0; j < 10; j++) f[j] = 0.0f;
#pragma unroll
    for (int b = 0; b < B_DIM; b++) {
        const float* p = g_part + (size_t)(b * C_DIM + c) * 10;
#pragma unroll
        for (int j = 0; j < 10; j++) f[j] += p[j];
    }

    const float invN = 1.0f / (float)N_PER_CH;
    float d[5];
    {
        float m  = f[0] * invN, M2 = f[1] * invN, M3 = f[2] * invN,
              M4 = f[3] * invN, M5 = f[4] * invN;
        float n  = f[5] * invN, T2 = f[6] * invN, T3 = f[7] * invN,
              T4 = f[8] * invN, T5 = f[9] * invN;

        float m2 = m * m, m3 = m2 * m;
        float mu2x = M2 - m2;
        float mu3x = M3 - 3.0f * m * M2 + 2.0f * m3;
        float mu4x = M4 - 4.0f * m * M3 + 6.0f * m2 * M2 - 3.0f * m2 * m2;
        float mu5x = M5 - 5.0f * m * M4 + 10.0f * m2 * M3 - 10.0f * m3 * M2
                     + 4.0f * m3 * m2;

        float n2 = n * n, n3 = n2 * n;
        float mu2t = T2 - n2;
        float mu3t = T3 - 3.0f * n * T2 + 2.0f * n3;
        float mu4t = T4 - 4.0f * n * T3 + 6.0f * n2 * T2 - 3.0f * n2 * n2;
        float mu5t = T5 - 5.0f * n * T4 + 10.0f * n2 * T3 - 10.0f * n3 * T2
                     + 4.0f * n3 * n2;

        d[0] = m - n;
        d[1] = mu2x - mu2t;
        d[2] = mu3x - mu3t;
        d[3] = mu4x - mu4t;
        d[4] = mu5x - mu5t;
    }

    __shared__ float fred[5][C_DIM];
#pragma unroll
    for (int i = 0; i < 5; i++) fred[i][c] = d[i] * d[i];
    __syncthreads();

    for (int off = 128; off > 0; off >>= 1) {
        if (c < off) {
#pragma unroll
            for (int i = 0; i < 5; i++) fred[i][c] += fred[i][c + off];
        }
        __syncthreads();
    }

    if (c == 0) {
        out[0] = sqrtf(fred[0][0]) + sqrtf(fred[1][0]) + sqrtf(fred[2][0]) +
                 sqrtf(fred[3][0]) + sqrtf(fred[4][0]);
    }
}

extern "C" void kernel_launch(void* const* d_in, const int* in_sizes, int n_in,
                              void* d_out, int out_size) {
    const float* x = (const float*)d_in[0];
    const float* t = (const float*)d_in[1];
    float* out = (float*)d_out;
    style_fused<<<N_CTA, 256>>>(x, t, out);
}

// round 4
// speedup vs baseline: 1.0799x; 1.0799x over previous
#include <cuda_runtime.h>
#include <cuda_bf16.h>
#include <math.h>

// StyleLoss: x, target [B=8, C=256, H=128, W=128] fp32.
// loss = sum_{k=1..5} sqrt( sum_c (mu_k_x[c] - mu_k_t[c])^2 )
//
// R4: cp.async.bulk (TMA) double-buffered pipeline -> SMEM -> FFMA2 power
// sums. Decouples memory-level parallelism from the register file: in-flight
// bytes = NSTAGES * CHUNK per CTA instead of (few) register-resident LDGs.
// Raw power sums S1..S5 per channel; binomial conversion to central moments
// in a fused last-block finalize.

#define B_DIM 8
#define C_DIM 256
#define HW_DIM (128 * 128)          // 16384 contiguous floats per (b,c) slice
#define N_PER_CH (B_DIM * HW_DIM)   // 131072 elements reduced per channel
#define N_CTA (B_DIM * C_DIM)       // 2048 blocks, one per (b,c) slice

#define CHUNK_BYTES 8192
#define CHUNK_FLOATS (CHUNK_BYTES / 4)   // 2048
#define NSTAGES 4
#define NCHUNKS 16                        // 8 x-chunks then 8 t-chunks
#define XCHUNKS 8

// Per-CTA partial sums: [cta][10] = {S1..S5 of x, S1..S5 of target}.
__device__ float g_part[N_CTA * 10];
__device__ unsigned int g_count;    // zero-init at load; last block resets it

typedef unsigned long long u64;

// ---- packed f32x2 math ----
#define MUL2(d, a, b) \
    asm("mul.rn.f32x2 %0, %1, %2;" : "=l"(d) : "l"(a), "l"(b))
#define ADD2(d, a, b) \
    asm("add.rn.f32x2 %0, %1, %2;" : "=l"(d) : "l"(a), "l"(b))
#define FMA2(d, a, b, c) \
    asm("fma.rn.f32x2 %0, %1, %2, %3;" : "=l"(d) : "l"(a), "l"(b), "l"(c))
#define UNPACK2(lo, hi, p) \
    asm("mov.b64 {%0, %1}, %2;" : "=f"(lo), "=f"(hi) : "l"(p))

// 5 power sums of a packed pair: 7 f32x2 ops for 2 elements.
__device__ __forceinline__ void acc5p(u64 v, u64* s) {
    u64 v2, v3;
    MUL2(v2, v, v);
    ADD2(s[0], s[0], v);
    FMA2(s[1], v, v, s[1]);
    FMA2(s[2], v2, v, s[2]);
    FMA2(s[3], v2, v2, s[3]);
    MUL2(v3, v2, v);
    FMA2(s[4], v3, v2, s[4]);
}

// ---- mbarrier / bulk-copy plumbing ----
__device__ __forceinline__ unsigned int smem_u32(const void* p) {
    unsigned int a;
    asm("{ .reg .u64 t; cvta.to.shared.u64 t, %1; cvt.u32.u64 %0, t; }"
        : "=r"(a) : "l"(p));
    return a;
}

#define MBAR_INIT(addr, count) \
    asm volatile("mbarrier.init.shared.b64 [%0], %1;" \
                 :: "r"(addr), "r"(count) : "memory")
#define MBAR_EXPECT_TX(addr, bytes) \
    asm volatile("mbarrier.arrive.expect_tx.shared.b64 _, [%0], %1;" \
                 :: "r"(addr), "r"(bytes) : "memory")
#define MBAR_ARRIVE(addr) \
    asm volatile("mbarrier.arrive.shared.b64 _, [%0];" \
                 :: "r"(addr) : "memory")
#define BULK_G2S(dst, src, bytes, mbar) \
    asm volatile("cp.async.bulk.shared::cluster.global.mbarrier::complete_tx::bytes " \
                 "[%0], [%1], %2, [%3];" \
                 :: "r"(dst), "l"(src), "r"(bytes), "r"(mbar) : "memory")
#define FENCE_PROXY() \
    asm volatile("fence.proxy.async.shared::cta;" ::: "memory")

#define MBAR_WAIT_PARITY(mbar_addr, phase_parity) do {                        \
    unsigned int _mbar = (mbar_addr);                                         \
    unsigned int _par  = (phase_parity);                                      \
    unsigned int _done;                                                       \
    asm volatile(                                                             \
        "{\n\t.reg .pred p;\n\t"                                              \
        "mbarrier.try_wait.parity.acquire.cta.shared::cta.b64 p, [%1], %2;\n\t" \
        "selp.b32 %0, 1, 0, p;\n\t}"                                          \
        : "=r"(_done) : "r"(_mbar), "r"(_par) : "memory");                    \
    if (!_done) {                                                             \
        asm volatile(                                                         \
            "{\n\t.reg .pred P1;\n\t"                                         \
            "WAIT_LOOP_%=:\n\t"                                               \
            "mbarrier.try_wait.parity.acquire.cta.shared::cta.b64 P1, [%0], %1, 0x989680;\n\t" \
            "@P1 bra.uni WAIT_DONE_%=;\n\t"                                   \
            "bra.uni WAIT_LOOP_%=;\n\t"                                       \
            "WAIT_DONE_%=:\n\t}"                                              \
            :: "r"(_mbar), "r"(_par) : "memory");                             \
    }                                                                         \
} while (0)

__global__ __launch_bounds__(256) void style_fused(
        const float* __restrict__ x,
        const float* __restrict__ t,
        float* __restrict__ out) {
    __shared__ __align__(128) float buf[NSTAGES][CHUNK_FLOATS];   // 32 KB ring
    __shared__ __align__(8)  u64   mbar[2 * NSTAGES];  // full[4] then empty[4]
    __shared__ float wred[8][10];
    __shared__ int is_last;

    const int tid = threadIdx.x;
    const int cta = blockIdx.x;  // cta = b*C + c -> contiguous HW slice

    const unsigned int mb   = smem_u32(mbar);              // full(s) = mb + 8s
    const unsigned int mbe  = mb + NSTAGES * 8;            // empty(s) = mbe + 8s
    const unsigned int bufb = smem_u32(buf);

    if (tid == 0) {
#pragma unroll
        for (int s = 0; s < NSTAGES; s++) {
            MBAR_INIT(mb  + s * 8, 1);    // producer's expect_tx arrive + tx
            MBAR_INIT(mbe + s * 8, 256);  // all consumers arrive
        }
        FENCE_PROXY();
    }
    __syncthreads();

    const u64 xg = (u64)(x + (size_t)cta * HW_DIM);
    const u64 tg = (u64)(t + (size_t)cta * HW_DIM);

    // Prologue: fill all stages (chunks 0..3, all from x).
    if (tid == 0) {
#pragma unroll
        for (int j = 0; j < NSTAGES; j++) {
            MBAR_EXPECT_TX(mb + j * 8, CHUNK_BYTES);
            BULK_G2S(bufb + j * CHUNK_BYTES, xg + (u64)j * CHUNK_BYTES,
                     CHUNK_BYTES, mb + j * 8);
        }
    }

    u64 sp[10];
#pragma unroll
    for (int j = 0; j < 10; j++) sp[j] = 0ull;

    for (int k = 0; k < NCHUNKS; k++) {
        const int st = k & (NSTAGES - 1);
        const unsigned int fullb  = mb  + st * 8;
        const unsigned int emptyb = mbe + st * 8;

        // Wait for chunk k's data (acquire orders the smem reads below).
        MBAR_WAIT_PARITY(fullb, (k >> 2) & 1);

        const ulonglong2* bp = reinterpret_cast<const ulonglong2*>(buf[st]);
        ulonglong2 a = bp[tid];
        ulonglong2 b = bp[tid + 256];
        u64* s = (k < XCHUNKS) ? sp : sp + 5;
        acc5p(a.x, s); acc5p(a.y, s); acc5p(b.x, s); acc5p(b.y, s);

        MBAR_ARRIVE(emptyb);

        // Producer: refill this stage with chunk k+NSTAGES once drained.
        if (tid == 0) {
            const int j = k + NSTAGES;
            if (j < NCHUNKS) {
                MBAR_WAIT_PARITY(emptyb, ((j >> 2) + 1) & 1);
                u64 src = (j < XCHUNKS)
                              ? xg + (u64)j * CHUNK_BYTES
                              : tg + (u64)(j - XCHUNKS) * CHUNK_BYTES;
                MBAR_EXPECT_TX(fullb, CHUNK_BYTES);
                BULK_G2S(bufb + st * CHUNK_BYTES, src, CHUNK_BYTES, fullb);
            }
        }
    }

    // Unpack pairs, warp tree-reduce the 10 scalar accumulators.
    float s[10];
#pragma unroll
    for (int j = 0; j < 10; j++) {
        float lo, hi;
        UNPACK2(lo, hi, sp[j]);
        s[j] = lo + hi;
    }
#pragma unroll
    for (int j = 0; j < 10; j++) {
#pragma unroll
        for (int o = 16; o > 0; o >>= 1)
            s[j] += __shfl_down_sync(0xffffffffu, s[j], o);
    }

    const int lane = tid & 31;
    const int wid  = tid >> 5;
    if (lane == 0) {
#pragma unroll
        for (int j = 0; j < 10; j++) wred[wid][j] = s[j];
    }
    __syncthreads();

    if (tid < 10) {
        float v = 0.0f;
#pragma unroll
        for (int w = 0; w < 8; w++) v += wred[w][tid];
        g_part[cta * 10 + tid] = v;
    }

    // ---- last-block fused finalize ----
    if (tid == 0) {
        __threadfence();  // publish g_part before counting
        unsigned int prev = atomicAdd(&g_count, 1u);
        is_last = (prev == (unsigned int)(N_CTA - 1)) ? 1 : 0;
    }
    __syncthreads();
    if (!is_last) return;

    if (tid == 0) g_count = 0;  // reset for next graph replay
    __threadfence();             // acquire: see all g_part writes

    const int c = tid;  // one thread per channel
    float f[10];
#pragma unroll
    for (int j = 0; j < 10; j++) f[j] = 0.0f;
#pragma unroll
    for (int b = 0; b < B_DIM; b++) {
        const float* p = g_part + (size_t)(b * C_DIM + c) * 10;
#pragma unroll
        for (int j = 0; j < 10; j++) f[j] += p[j];
    }

    const float invN = 1.0f / (float)N_PER_CH;
    float d[5];
    {
        float m  = f[0] * invN, M2 = f[1] * invN, M3 = f[2] * invN,
              M4 = f[3] * invN, M5 = f[4] * invN;
        float n  = f[5] * invN, T2 = f[6] * invN, T3 = f[7] * invN,
              T4 = f[8] * invN, T5 = f[9] * invN;

        float m2 = m * m, m3 = m2 * m;
        float mu2x = M2 - m2;
        float mu3x = M3 - 3.0f * m * M2 + 2.0f * m3;
        float mu4x = M4 - 4.0f * m * M3 + 6.0f * m2 * M2 - 3.0f * m2 * m2;
        float mu5x = M5 - 5.0f * m * M4 + 10.0f * m2 * M3 - 10.0f * m3 * M2
                     + 4.0f * m3 * m2;

        float n2 = n * n, n3 = n2 * n;
        float mu2t = T2 - n2;
        float mu3t = T3 - 3.0f * n * T2 + 2.0f * n3;
        float mu4t = T4 - 4.0f * n * T3 + 6.0f * n2 * T2 - 3.0f * n2 * n2;
        float mu5t = T5 - 5.0f * n * T4 + 10.0f * n2 * T3 - 10.0f * n3 * T2
                     + 4.0f * n3 * n2;

        d[0] = m - n;
        d[1] = mu2x - mu2t;
        d[2] = mu3x - mu3t;
        d[3] = mu4x - mu4t;
        d[4] = mu5x - mu5t;
    }

    // Reuse the (now idle) stream buffer for the cross-channel reduction.
    float (*fred)[C_DIM] = reinterpret_cast<float (*)[C_DIM]>(&buf[0][0]);
#pragma unroll
    for (int i = 0; i < 5; i++) fred[i][c] = d[i] * d[i];
    __syncthreads();

    for (int off = 128; off > 0; off >>= 1) {
        if (c < off) {
#pragma unroll
            for (int i = 0; i < 5; i++) fred[i][c] += fred[i][c + off];
        }
        __syncthreads();
    }

    if (c == 0) {
        out[0] = sqrtf(fred[0][0]) + sqrtf(fred[1][0]) + sqrtf(fred[2][0]) +
                 sqrtf(fred[3][0]) + sqrtf(fred[4][0]);
    }
}

extern "C" void kernel_launch(void* const* d_in, const int* in_sizes, int n_in,
                              void* d_out, int out_size) {
    const float* x = (const float*)d_in[0];
    const float* t = (const float*)d_in[1];
    float* out = (float*)d_out;
    style_fused<<<N_CTA, 256>>>(x, t, out);
}

// round 5
// speedup vs baseline: 1.1989x; 1.1102x over previous
#include <cuda_runtime.h>
#include <cuda_bf16.h>
#include <math.h>

// StyleLoss: x, target [B=8, C=256, H=128, W=128] fp32.
// loss = sum_{k=1..5} sqrt( sum_c (mu_k_x[c] - mu_k_t[c])^2 )
//
// R5: single-wave persistent grid (512 CTAs, 4/SM) + cp.async.bulk 4-stage
// ring + FFMA2 power sums. Each CTA streams 4 (b,c) slices of x and t
// (512 KB) for one channel; eliminates the 3.4-wave tail that capped DRAM
// at ~67%. Raw power sums S1..S5 -> central moments in fused last-block
// finalize.

#define B_DIM 8
#define C_DIM 256
#define HW_DIM (128 * 128)          // 16384 contiguous floats per (b,c) slice
#define N_PER_CH (B_DIM * HW_DIM)   // 131072 elements reduced per channel
#define N_GRID 512                   // single co-resident wave at occ 4
#define SLICES_PER_CTA 4             // 4 b-values per CTA

#define CHUNK_BYTES 8192
#define CHUNK_FLOATS (CHUNK_BYTES / 4)   // 2048
#define NSTAGES 4
// Per CTA: 4 slices x (8 x-chunks + 8 t-chunks) = 64 chunks.
#define NCHUNKS_TOTAL 64

// Per-CTA partial sums: [cta][10] = {S1..S5 of x, S1..S5 of target}.
__device__ float g_part[N_GRID * 10];
__device__ unsigned int g_count;    // zero-init at load; last block resets it

typedef unsigned long long u64;

// ---- packed f32x2 math ----
#define MUL2(d, a, b) \
    asm("mul.rn.f32x2 %0, %1, %2;" : "=l"(d) : "l"(a), "l"(b))
#define ADD2(d, a, b) \
    asm("add.rn.f32x2 %0, %1, %2;" : "=l"(d) : "l"(a), "l"(b))
#define FMA2(d, a, b, c) \
    asm("fma.rn.f32x2 %0, %1, %2, %3;" : "=l"(d) : "l"(a), "l"(b), "l"(c))
#define UNPACK2(lo, hi, p) \
    asm("mov.b64 {%0, %1}, %2;" : "=f"(lo), "=f"(hi) : "l"(p))

// 5 power sums of a packed pair: 7 f32x2 ops for 2 elements.
__device__ __forceinline__ void acc5p(u64 v, u64* s) {
    u64 v2, v3;
    MUL2(v2, v, v);
    ADD2(s[0], s[0], v);
    FMA2(s[1], v, v, s[1]);
    FMA2(s[2], v2, v, s[2]);
    FMA2(s[3], v2, v2, s[3]);
    MUL2(v3, v2, v);
    FMA2(s[4], v3, v2, s[4]);
}

// ---- mbarrier / bulk-copy plumbing ----
__device__ __forceinline__ unsigned int smem_u32(const void* p) {
    unsigned int a;
    asm("{ .reg .u64 t; cvta.to.shared.u64 t, %1; cvt.u32.u64 %0, t; }"
        : "=r"(a) : "l"(p));
    return a;
}

#define MBAR_INIT(addr, count) \
    asm volatile("mbarrier.init.shared.b64 [%0], %1;" \
                 :: "r"(addr), "r"(count) : "memory")
#define MBAR_EXPECT_TX(addr, bytes) \
    asm volatile("mbarrier.arrive.expect_tx.shared.b64 _, [%0], %1;" \
                 :: "r"(addr), "r"(bytes) : "memory")
#define MBAR_ARRIVE(addr) \
    asm volatile("mbarrier.arrive.shared.b64 _, [%0];" \
                 :: "r"(addr) : "memory")
#define BULK_G2S(dst, src, bytes, mbar) \
    asm volatile("cp.async.bulk.shared::cluster.global.mbarrier::complete_tx::bytes " \
                 "[%0], [%1], %2, [%3];" \
                 :: "r"(dst), "l"(src), "r"(bytes), "r"(mbar) : "memory")
#define FENCE_PROXY() \
    asm volatile("fence.proxy.async.shared::cta;" ::: "memory")

#define MBAR_WAIT_PARITY(mbar_addr, phase_parity) do {                        \
    unsigned int _mbar = (mbar_addr);                                         \
    unsigned int _par  = (phase_parity);                                      \
    unsigned int _done;                                                       \
    asm volatile(                                                             \
        "{\n\t.reg .pred p;\n\t"                                              \
        "mbarrier.try_wait.parity.acquire.cta.shared::cta.b64 p, [%1], %2;\n\t" \
        "selp.b32 %0, 1, 0, p;\n\t}"                                          \
        : "=r"(_done) : "r"(_mbar), "r"(_par) : "memory");                    \
    if (!_done) {                                                             \
        asm volatile(                                                         \
            "{\n\t.reg .pred P1;\n\t"                                         \
            "WAIT_LOOP_%=:\n\t"                                               \
            "mbarrier.try_wait.parity.acquire.cta.shared::cta.b64 P1, [%0], %1, 0x989680;\n\t" \
            "@P1 bra.uni WAIT_DONE_%=;\n\t"                                   \
            "bra.uni WAIT_LOOP_%=;\n\t"                                       \
            "WAIT_DONE_%=:\n\t}"                                              \
            :: "r"(_mbar), "r"(_par) : "memory");                             \
    }                                                                         \
} while (0)

__global__ __launch_bounds__(256, 4) void style_fused(
        const float* __restrict__ x,
        const float* __restrict__ t,
        float* __restrict__ out) {
    __shared__ __align__(128) float buf[NSTAGES][CHUNK_FLOATS];   // 32 KB ring
    __shared__ __align__(8)  u64   mbar[2 * NSTAGES];  // full[4] then empty[4]
    __shared__ float wred[8][10];
    __shared__ int is_last;

    const int tid = threadIdx.x;
    const int cta = blockIdx.x;
    const int c   = cta & (C_DIM - 1);   // channel
    const int b0  = cta >> 8;            // 0 or 1: batch half

    const unsigned int mb   = smem_u32(mbar);              // full(s) = mb + 8s
    const unsigned int mbe  = mb + NSTAGES * 8;            // empty(s) = mbe + 8s
    const unsigned int bufb = smem_u32(buf);

    if (tid == 0) {
#pragma unroll
        for (int s = 0; s < NSTAGES; s++) {
            MBAR_INIT(mb  + s * 8, 1);    // producer's expect_tx arrive + tx
            MBAR_INIT(mbe + s * 8, 256);  // all consumers arrive
        }
        FENCE_PROXY();
    }
    __syncthreads();

    // Chunk j (0..63): sb = j>>4 (which of 4 b-slices), tensor = (j>>3)&1
    // (0 = x, 1 = t), off = j&7 (8 KB chunk within the 64 KB slice).
    // Slice index in the flat [B,C] layout: (b0*4 + sb)*256 + c.
#define CHUNK_SRC(j)                                                        \
    ((u64)((((j >> 3) & 1) ? t : x) +                                       \
           (size_t)((b0 * SLICES_PER_CTA + ((j) >> 4)) * C_DIM + c) *       \
               HW_DIM +                                                     \
           (size_t)((j) & 7) * CHUNK_FLOATS))

    // Prologue: fill all stages with chunks 0..3.
    if (tid == 0) {
#pragma unroll
        for (int j = 0; j < NSTAGES; j++) {
            MBAR_EXPECT_TX(mb + j * 8, CHUNK_BYTES);
            BULK_G2S(bufb + j * CHUNK_BYTES, CHUNK_SRC(j), CHUNK_BYTES,
                     mb + j * 8);
        }
    }

    u64 sp[10];
#pragma unroll
    for (int j = 0; j < 10; j++) sp[j] = 0ull;

    for (int k4 = 0; k4 < NCHUNKS_TOTAL / NSTAGES; k4++) {
        const int par = k4 & 1;
        // Within one k4 group all 4 chunks belong to the same tensor:
        // tensor = (k4>>1)&1.
        u64* s = ((k4 >> 1) & 1) ? sp + 5 : sp;
#pragma unroll
        for (int st = 0; st < NSTAGES; st++) {
            const int j = k4 * NSTAGES + st;
            const unsigned int fullb  = mb  + st * 8;
            const unsigned int emptyb = mbe + st * 8;

            MBAR_WAIT_PARITY(fullb, par);

            const ulonglong2* bp =
                reinterpret_cast<const ulonglong2*>(buf[st]);
            ulonglong2 a = bp[tid];
            ulonglong2 b = bp[tid + 256];
            acc5p(a.x, s); acc5p(a.y, s); acc5p(b.x, s); acc5p(b.y, s);

            MBAR_ARRIVE(emptyb);

            // Refill this stage with chunk j+NSTAGES once drained.
            if (tid == 0 && j + NSTAGES < NCHUNKS_TOTAL) {
                MBAR_WAIT_PARITY(emptyb, par);
                const int jn = j + NSTAGES;
                MBAR_EXPECT_TX(fullb, CHUNK_BYTES);
                BULK_G2S(bufb + st * CHUNK_BYTES, CHUNK_SRC(jn), CHUNK_BYTES,
                         fullb);
            }
        }
    }
#undef CHUNK_SRC

    // Unpack pairs, warp tree-reduce the 10 scalar accumulators.
    float s[10];
#pragma unroll
    for (int j = 0; j < 10; j++) {
        float lo, hi;
        UNPACK2(lo, hi, sp[j]);
        s[j] = lo + hi;
    }
#pragma unroll
    for (int j = 0; j < 10; j++) {
#pragma unroll
        for (int o = 16; o > 0; o >>= 1)
            s[j] += __shfl_down_sync(0xffffffffu, s[j], o);
    }

    const int lane = tid & 31;
    const int wid  = tid >> 5;
    if (lane == 0) {
#pragma unroll
        for (int j = 0; j < 10; j++) wred[wid][j] = s[j];
    }
    __syncthreads();

    if (tid < 10) {
        float v = 0.0f;
#pragma unroll
        for (int w = 0; w < 8; w++) v += wred[w][tid];
        g_part[cta * 10 + tid] = v;
    }

    // ---- last-block fused finalize ----
    if (tid == 0) {
        __threadfence();  // publish g_part before counting
        unsigned int prev = atomicAdd(&g_count, 1u);
        is_last = (prev == (unsigned int)(N_GRID - 1)) ? 1 : 0;
    }
    __syncthreads();
    if (!is_last) return;

    if (tid == 0) g_count = 0;  // reset for next graph replay
    __threadfence();             // acquire: see all g_part writes

    const int ch = tid;  // one thread per channel
    float f[10];
#pragma unroll
    for (int j = 0; j < 10; j++)
        f[j] = g_part[ch * 10 + j] + g_part[(ch + C_DIM) * 10 + j];

    const float invN = 1.0f / (float)N_PER_CH;
    float d[5];
    {
        float m  = f[0] * invN, M2 = f[1] * invN, M3 = f[2] * invN,
              M4 = f[3] * invN, M5 = f[4] * invN;
        float n  = f[5] * invN, T2 = f[6] * invN, T3 = f[7] * invN,
              T4 = f[8] * invN, T5 = f[9] * invN;

        float m2 = m * m, m3 = m2 * m;
        float mu2x = M2 - m2;
        float mu3x = M3 - 3.0f * m * M2 + 2.0f * m3;
        float mu4x = M4 - 4.0f * m * M3 + 6.0f * m2 * M2 - 3.0f * m2 * m2;
        float mu5x = M5 - 5.0f * m * M4 + 10.0f * m2 * M3 - 10.0f * m3 * M2
                     + 4.0f * m3 * m2;

        float n2 = n * n, n3 = n2 * n;
        float mu2t = T2 - n2;
        float mu3t = T3 - 3.0f * n * T2 + 2.0f * n3;
        float mu4t = T4 - 4.0f * n * T3 + 6.0f * n2 * T2 - 3.0f * n2 * n2;
        float mu5t = T5 - 5.0f * n * T4 + 10.0f * n2 * T3 - 10.0f * n3 * T2
                     + 4.0f * n3 * n2;

        d[0] = m - n;
        d[1] = mu2x - mu2t;
        d[2] = mu3x - mu3t;
        d[3] = mu4x - mu4t;
        d[4] = mu5x - mu5t;
    }

    // Reuse the (now idle) stream buffer for the cross-channel reduction.
    float (*fred)[C_DIM] = reinterpret_cast<float (*)[C_DIM]>(&buf[0][0]);
#pragma unroll
    for (int i = 0; i < 5; i++) fred[i][ch] = d[i] * d[i];
    __syncthreads();

    for (int off = 128; off > 0; off >>= 1) {
        if (ch < off) {
#pragma unroll
            for (int i = 0; i < 5; i++) fred[i][ch] += fred[i][ch + off];
        }
        __syncthreads();
    }

    if (ch == 0) {
        out[0] = sqrtf(fred[0][0]) + sqrtf(fred[1][0]) + sqrtf(fred[2][0]) +
                 sqrtf(fred[3][0]) + sqrtf(fred[4][0]);
    }
}

extern "C" void kernel_launch(void* const* d_in, const int* in_sizes, int n_in,
                              void* d_out, int out_size) {
    const float* x = (const float*)d_in[0];
    const float* t = (const float*)d_in[1];
    float* out = (float*)d_out;
    style_fused<<<N_GRID, 256>>>(x, t, out);
}